// round 13
// baseline (speedup 1.0000x reference)
#include <cuda_runtime.h>
#include <cuda_bf16.h>
#include <cstdint>

#define BB 4
#define CI 256
#define CO 128
#define HH 56
#define WW 56
#define KK 49
#define KTOT (CI*KK)          // 12544
#define KC   64               // K per chunk
#define NCHUNK (KTOT/KC)      // 196
#define PXW  72               // padded x row width (bf16 elems)

typedef unsigned int u32;
typedef unsigned long long u64;

// ---------------- device scratch -------------------------------------------
// A in per-lane mma-fragment order: [q][wm][ks][mf][lane] uint4
__device__ __align__(16) uint4 g_AfH[NCHUNK*4*4*2*32];
__device__ __align__(16) uint4 g_AfL[NCHUNK*4*4*2*32];
__device__ __align__(16) __nv_bfloat16 g_xh[BB*CI*HH*PXW];
__device__ __align__(16) __nv_bfloat16 g_xl[BB*CI*HH*PXW];
__device__ float g_attn[BB*HH*KK*WW];

#define SWZ(o) ((o) ^ (((o) >> 3) & 0x70))

// ---------------- PTX helpers (baseline ISA, sm_80+) -----------------------
__device__ __forceinline__ u32 smem_u32(const void* p) {
    u32 a;
    asm("{ .reg .u64 t; cvta.to.shared.u64 t, %1; cvt.u32.u64 %0, t; }"
        : "=r"(a) : "l"(p));
    return a;
}
__device__ __forceinline__ void cpasync16(u32 dst, const void* src, u32 srcsize) {
    u64 gsrc = (u64)__cvta_generic_to_global(src);
    asm volatile("cp.async.cg.shared.global [%0], [%1], 16, %2;"
                 :: "r"(dst), "l"(gsrc), "r"(srcsize) : "memory");
}
#define CP_COMMIT() asm volatile("cp.async.commit_group;" ::: "memory")

__device__ __forceinline__ void ldm_x4(u32* r, u32 addr) {
    asm volatile("ldmatrix.sync.aligned.m8n8.x4.shared.b16 {%0,%1,%2,%3}, [%4];"
        : "=r"(r[0]), "=r"(r[1]), "=r"(r[2]), "=r"(r[3]) : "r"(addr));
}
__device__ __forceinline__ void ldm_x2(u32* r, u32 addr) {
    asm volatile("ldmatrix.sync.aligned.m8n8.x2.shared.b16 {%0,%1}, [%2];"
        : "=r"(r[0]), "=r"(r[1]) : "r"(addr));
}
__device__ __forceinline__ void mma16816(float* c, const u32* a, const u32* b) {
    asm volatile("mma.sync.aligned.m16n8k16.row.col.f32.bf16.bf16.f32 "
        "{%0,%1,%2,%3}, {%4,%5,%6,%7}, {%8,%9}, {%0,%1,%2,%3};"
        : "+f"(c[0]), "+f"(c[1]), "+f"(c[2]), "+f"(c[3])
        : "r"(a[0]), "r"(a[1]), "r"(a[2]), "r"(a[3]), "r"(b[0]), "r"(b[1]));
}
#define MB_INIT(mb, n) asm volatile("mbarrier.init.shared.b64 [%0], %1;" :: "r"(mb), "r"((u32)(n)) : "memory")
#define MB_ARRIVE(mb)  asm volatile("mbarrier.arrive.shared.b64 _, [%0];" :: "r"(mb) : "memory")

__device__ __forceinline__ void mb_wait(u32 mb, u32 parity) {
    asm volatile(
        "{\n\t.reg .pred P1;\n\t"
        "WL_%=:\n\t"
        "mbarrier.try_wait.parity.acquire.cta.shared::cta.b64 P1, [%0], %1, 0x989680;\n\t"
        "@P1 bra.uni WD_%=;\n\t"
        "bra.uni WL_%=;\n\t"
        "WD_%=:\n\t}"
        :: "r"(mb), "r"(parity) : "memory");
}

__device__ __forceinline__ unsigned short bfu(float v) {
    __nv_bfloat16 h = __float2bfloat16(v);
    return *(unsigned short*)&h;
}

// ---------------- prep: W1 -> bf16 hi/lo A fragments -----------------------
// grid (196, 4), block 256: tid -> ks(2b) mf(1b) lane(5b)
__global__ void k_prepw(const float* __restrict__ W1) {
    int q = blockIdx.x, wm = blockIdx.y;
    int tid = threadIdx.x;
    int ks = tid >> 6, mf = (tid >> 5) & 1, lane = tid & 31;
    int m  = wm * 32 + mf * 16 + (lane >> 2);
    int k0 = q * KC + ks * 16 + (lane & 3) * 2;
    const float* w0 = W1 + (size_t)m * KTOT + k0;
    const float* w1 = W1 + (size_t)(m + 8) * KTOT + k0;
    float v[8] = { w0[0], w0[1], w1[0], w1[1], w0[8], w0[9], w1[8], w1[9] };
    u32 h[4], l[4];
    #pragma unroll
    for (int i = 0; i < 4; i++) {
        float a = v[2*i], b = v[2*i+1];
        unsigned short ah = bfu(a), bh = bfu(b);
        float ar = a - __bfloat162float(*(__nv_bfloat16*)&ah);
        float br = b - __bfloat162float(*(__nv_bfloat16*)&bh);
        h[i] = (u32)ah | ((u32)bh << 16);
        l[i] = (u32)bfu(ar) | ((u32)bfu(br) << 16);
    }
    size_t off = ((((size_t)q * 4 + wm) * 4 + ks) * 2 + mf) * 32 + lane;
    g_AfH[off] = make_uint4(h[0], h[1], h[2], h[3]);
    g_AfL[off] = make_uint4(l[0], l[1], l[2], l[3]);
}

// ---------------- prep: x -> padded bf16 hi/lo planes ----------------------
__global__ void k_prepx(const float* __restrict__ x) {
    int idx = blockIdx.x * 128 + threadIdx.x;   // over BB*CI*HH rows
    if (idx >= BB * CI * HH) return;
    const float* row = x + (size_t)idx * WW;
    __align__(16) __nv_bfloat16 h[PXW], l[PXW];
    #pragma unroll
    for (int i = 0; i < PXW; i++) {
        int gx = i - 6;
        float v = (gx >= 0 && gx < WW) ? row[gx] : 0.f;
        __nv_bfloat16 hh = __float2bfloat16(v);
        h[i] = hh;
        l[i] = __float2bfloat16(v - __bfloat162float(hh));
    }
    uint4* dh = (uint4*)((char*)g_xh + (size_t)idx * PXW * 2);
    uint4* dl = (uint4*)((char*)g_xl + (size_t)idx * PXW * 2);
    #pragma unroll
    for (int s = 0; s < 9; s++) { dh[s] = ((uint4*)h)[s]; dl[s] = ((uint4*)l)[s]; }
}

// ---------------- conv1 + attn fused ---------------------------------------
// 384 threads: warps 0-7 consumers (mma), warps 8-11 producers (stage+gather)
// After mainloop: epilogue computes logits + softmax in-CTA -> g_attn.
#define XS_SZ  12096              // 84 rows * 144B
#define TILE_B 14336              // 112 rows * 128B
#define SM_XS  64                 // after 4 mbarriers
#define SM_B   (SM_XS + 4*XS_SZ)  // 48448
#define SM_TOTAL (SM_B + 2*2*TILE_B)   // 105792
// epilogue aliases: O1s (fp32 [128][112] = 57344B) over SM_B region;
// ls (49*112*4=21952) at SM_XS; W2s (49*128*4=25088) after ls.

__global__ void __launch_bounds__(384, 1) k_conv1(const float* __restrict__ b1,
                                                  const float* __restrict__ W2,
                                                  const float* __restrict__ b2) {
    extern __shared__ char smem[];
    u32 sb = smem_u32(smem);
    int tid = threadIdx.x, wid = tid >> 5, lane = tid & 31;
    int rp = blockIdx.x, b = blockIdx.y;
    int y0 = rp * 2;

    if (tid == 0) {
        MB_INIT(sb + 0, 128);  MB_INIT(sb + 8, 128);    // full[0], full[1]
        MB_INIT(sb + 16, 256); MB_INIT(sb + 24, 256);   // free[0], free[1]
    }
    __syncthreads();

    float acc[56];
    #pragma unroll
    for (int i = 0; i < 56; i++) acc[i] = 0.f;

    if (wid < 8) {
        // ======================= CONSUMERS =======================
        int wm = wid & 3, wn = wid >> 2;

        u32 xorm  = (u32)(lane & 7) << 4;
        u32 bRow4 = (u32)(wn * 56 + ((lane >> 4) << 3) + (lane & 7)) * 128;
        u32 bRow2 = (u32)(wn * 56 + 48 + (lane & 7)) * 128;
        u32 bCol  = (u32)((lane >> 3) & 1) * 16;
        u32 fullph[2] = {0, 0};

        for (int q = 0; q < NCHUNK; q++) {
            int p = q & 1;
            // prefetch A fragments for this chunk (overlaps the full-wait)
            const uint4* ph = g_AfH + ((size_t)q * 4 + wm) * 256 + lane;
            const uint4* pl = g_AfL + ((size_t)q * 4 + wm) * 256 + lane;
            uint4 AH[8], AL[8];          // s = ks*2+mf
            #pragma unroll
            for (int s = 0; s < 8; s++) { AH[s] = ph[s * 32]; AL[s] = pl[s * 32]; }

            mb_wait(sb + p * 8, fullph[p]); fullph[p] ^= 1;

            u32 Bh = sb + SM_B + p * (2 * TILE_B);
            u32 Bl = Bh + TILE_B;
            #pragma unroll
            for (int ks = 0; ks < 4; ks++) {
                u32 colB = ((u32)(ks * 32) + bCol) ^ xorm;
                u32 bh[14], bl[14];
                #pragma unroll
                for (int pp = 0; pp < 3; pp++) {
                    ldm_x4(&bh[4 * pp], Bh + bRow4 + pp * 2048 + colB);
                    ldm_x4(&bl[4 * pp], Bl + bRow4 + pp * 2048 + colB);
                }
                ldm_x2(&bh[12], Bh + bRow2 + colB);
                ldm_x2(&bl[12], Bl + bRow2 + colB);
                #pragma unroll
                for (int mf = 0; mf < 2; mf++) {
                    const u32* ah = (const u32*)&AH[ks * 2 + mf];
                    const u32* al = (const u32*)&AL[ks * 2 + mf];
                    #pragma unroll
                    for (int nf = 0; nf < 7; nf++) {
                        float* c = &acc[(mf * 7 + nf) * 4];
                        mma16816(c, ah, &bh[2 * nf]);
                        mma16816(c, ah, &bl[2 * nf]);
                        mma16816(c, al, &bh[2 * nf]);
                    }
                }
            }
            MB_ARRIVE(sb + 16 + p * 8);
        }
    } else {
        // ======================= PRODUCERS (4 warps, 128 threads) =========
        int ptid = tid - 256;     // 0..127

        auto stage_xs = [&](int q) {
            int c0 = (q * KC) / KK;
            u32 xb = sb + SM_XS + (q & 3) * XS_SZ;
            for (int s = ptid; s < 756; s += 128) {
                int rowi = s / 9, seg = s % 9;
                int trm = rowi / 42, rem = rowi % 42, cc = rem / 14, r = rem % 14;
                int cp = c0 + cc, gy = y0 - 6 + r;
                bool v = (gy >= 0 && gy < HH && cp < CI);
                const char* base = trm ? (const char*)g_xl : (const char*)g_xh;
                const char* src = base +
                    ((size_t)((b * CI + (v ? cp : 0)) * HH + (v ? gy : 0)) * PXW) * 2 + seg * 16;
                cpasync16(xb + ((trm * 3 + cc) * 14 + r) * 144 + seg * 16, src, v ? 16u : 0u);
            }
        };

        stage_xs(0); CP_COMMIT();
        stage_xs(1); CP_COMMIT();
        u32 freeph[2] = {0, 0};

        for (int q = 0; q < NCHUNK; q++) {
            int p = q & 1;
            if (q >= 2) { mb_wait(sb + 16 + p * 8, freeph[p]); freeph[p] ^= 1; }
            if (q + 2 < NCHUNK) stage_xs(q + 2);
            CP_COMMIT();
            asm volatile("cp.async.wait_group 2;" ::: "memory");
            asm volatile("bar.sync 1, 128;" ::: "memory");   // producer-group barrier

            // gather B[q] on 128 threads
            int k0 = q * KC, c0 = k0 / KK, t00 = k0 - KK * c0;
            const char* xbase = smem + SM_XS + (q & 3) * XS_SZ;
            char* Bt0 = smem + SM_B + p * (2 * TILE_B);
            for (int row = ptid; row < 224; row += 128) {
                int gterm = row / 112, gn = row % 112;
                int gdy = gn / 56, gxn = gn % 56;
                int tj = t00 % 7;
                const char* xsrc = xbase + gterm * 6048;
                int idx = (gdy + 2 * (t00 / 7)) * PXW + gxn + 2 * tj;
                char* Bt = Bt0 + gterm * TILE_B;
                u32 rowoff = (u32)(gn * 128);
                #pragma unroll
                for (int g = 0; g < 8; g++) {
                    u32 v[4];
                    #pragma unroll
                    for (int h2 = 0; h2 < 4; h2++) {
                        u32 a = *(const unsigned short*)(xsrc + idx * 2);
                        idx += (tj == 6) ? 132 : 2; tj = (tj == 6) ? 0 : tj + 1;
                        u32 bb = *(const unsigned short*)(xsrc + idx * 2);
                        idx += (tj == 6) ? 132 : 2; tj = (tj == 6) ? 0 : tj + 1;
                        v[h2] = a | (bb << 16);
                    }
                    *(uint4*)(Bt + SWZ(rowoff + g * 16)) = *(uint4*)v;
                }
            }
            MB_ARRIVE(sb + p * 8);   // full[p]
        }
    }

    // ======================= FUSED ATTN EPILOGUE =======================
    __syncthreads();    // everyone done; B buffers + xs now dead
    {
        float* O1s = (float*)(smem + SM_B);                        // [128][112]
        float* ls  = (float*)(smem + SM_XS);                       // [49][112]
        float* W2s = (float*)(smem + SM_XS + 49 * 112 * 4);        // [49][128]

        if (wid < 8) {
            int wm = wid & 3, wn = wid >> 2;
            #pragma unroll
            for (int mf = 0; mf < 2; mf++) {
                int m = wm * 32 + mf * 16 + (lane >> 2);
                float bia0 = b1[m], bia8 = b1[m + 8];
                #pragma unroll
                for (int nf = 0; nf < 7; nf++) {
                    float* c = &acc[(mf * 7 + nf) * 4];
                    int n = wn * 56 + nf * 8 + 2 * (lane & 3);
                    O1s[m * 112 + n]           = c[0] + bia0;
                    O1s[m * 112 + n + 1]       = c[1] + bia0;
                    O1s[(m + 8) * 112 + n]     = c[2] + bia8;
                    O1s[(m + 8) * 112 + n + 1] = c[3] + bia8;
                }
            }
        }
        for (int s = tid; s < (KK * CO) / 4; s += 384)
            *(float4*)&W2s[4 * s] = *(const float4*)&W2[4 * s];
        __syncthreads();

        // logits: ls[k][n] = b2[k] + sum_c W2[k][c] * O1s[c][n]
        for (int p = tid; p < KK * 112; p += 384) {
            int k = p / 112, n = p - k * 112;
            float a = b2[k];
            const float* wrow = &W2s[k * 128];
            #pragma unroll 4
            for (int c = 0; c < 128; c++)
                a += wrow[c] * O1s[c * 112 + n];
            ls[p] = a;
        }
        __syncthreads();

        // softmax over k, per column n; write g_attn
        if (tid < 112) {
            int n = tid;
            float mx = -1e30f;
            #pragma unroll
            for (int k = 0; k < KK; k++) mx = fmaxf(mx, ls[k * 112 + n]);
            float ssum = 0.f;
            #pragma unroll
            for (int k = 0; k < KK; k++) {
                float e = __expf(ls[k * 112 + n] - mx);
                ls[k * 112 + n] = e;
                ssum += e;
            }
            float inv = 1.f / ssum;
            int row = n / 56, xc = n - (n / 56) * 56;
            float* ga = g_attn + (size_t)(b * HH + y0 + row) * KK * WW;
            #pragma unroll
            for (int k = 0; k < KK; k++)
                ga[k * WW + xc] = ls[k * 112 + n] * inv;
        }
    }
}

// ---------------- k_wsum: weighted patch sum (16-ch chunk per block) -------
// grid (16, 56, 4), 224 threads. smem: as[49*56] + xs[16*7*72] = 43232 B.
// Low-register loop order: tap-outer, 4 channels inner.
#define WS_SMEM ((49*56 + 16*7*72) * 4)   // 43232 B

__global__ void __launch_bounds__(224) k_wsum(const float* __restrict__ x,
                                              float* __restrict__ out) {
    extern __shared__ float sm[];
    float* as = sm;              // [49][56] attn
    float* xs = sm + 49 * 56;    // [16*7][72]

    int tid = threadIdx.x;
    int cg = blockIdx.x, y = blockIdx.y, b = blockIdx.z;

    const float* ga = g_attn + (size_t)(b * HH + y) * KK * WW;
    for (int s = tid; s < KK * WW; s += 224) as[s] = ga[s];

    for (int s = tid; s < 16 * 7 * 34; s += 224) {
        int c  = s / (7 * 34);
        int i  = (s / 34) % 7;
        int s2 = s % 34;
        int gx = 2 * s2 - 6;
        int gy = y - 6 + 2 * i;
        float2 v = make_float2(0.f, 0.f);
        if (gy >= 0 && gy < HH && gx >= 0 && gx < WW) {
            v = *reinterpret_cast<const float2*>(
                &x[(size_t)((b * CI + cg * 16 + c) * HH + gy) * WW + gx]);
        }
        *reinterpret_cast<float2*>(&xs[(c * 7 + i) * 72 + 2 * s2]) = v;
    }
    __syncthreads();

    int cl = tid / WW;           // 0..3 -> channels cl*4 .. cl*4+3
    int xc = tid % WW;

    float acc[4] = {0.f, 0.f, 0.f, 0.f};
    const float* xbase = &xs[(cl * 4) * 7 * 72 + xc];

    #pragma unroll
    for (int i = 0; i < 7; i++) {
        #pragma unroll
        for (int j = 0; j < 7; j++) {
            float a = as[(7 * i + j) * WW + xc];
            #pragma unroll
            for (int q = 0; q < 4; q++)
                acc[q] += a * xbase[(q * 7 + i) * 72 + 2 * j];
        }
    }

    #pragma unroll
    for (int q = 0; q < 4; q++) {
        int c = cg * 16 + cl * 4 + q;
        out[(size_t)((b * CI + c) * HH + y) * WW + xc] = acc[q];
    }
}

// ---------------------------------------------------------------------------
extern "C" void kernel_launch(void* const* d_in, const int* in_sizes, int n_in,
                              void* d_out, int out_size) {
    const float* x  = (const float*)d_in[0];
    const float* W1 = (const float*)d_in[1];
    const float* b1 = (const float*)d_in[2];
    const float* W2 = (const float*)d_in[3];
    const float* b2 = (const float*)d_in[4];
    float* out = (float*)d_out;
    (void)in_sizes; (void)n_in; (void)out_size;

    k_prepw<<<dim3(NCHUNK, 4), 256>>>(W1);
    k_prepx<<<(BB * CI * HH + 127) / 128, 128>>>(x);

    cudaFuncSetAttribute(k_conv1, cudaFuncAttributeMaxDynamicSharedMemorySize,
                         SM_TOTAL);
    dim3 g1(28, BB);
    k_conv1<<<g1, 384, SM_TOTAL>>>(b1, W2, b2);

    cudaFuncSetAttribute(k_wsum, cudaFuncAttributeMaxDynamicSharedMemorySize,
                         WS_SMEM);
    dim3 g3(16, HH, BB);
    k_wsum<<<g3, 224, WS_SMEM>>>(x, out);
}

// round 16
// speedup vs baseline: 1.3676x; 1.3676x over previous
#include <cuda_runtime.h>
#include <cuda_fp16.h>
#include <cstdint>

#define BB 4
#define CI 256
#define CO 128
#define HH 56
#define WW 56
#define KK 49
#define KTOT (CI*KK)          // 12544
#define KC   64               // K per chunk
#define NCHUNK (KTOT/KC)      // 196
#define PXW  72               // padded x row width (fp16 elems)

typedef unsigned int u32;
typedef unsigned long long u64;

// ---------------- device scratch -------------------------------------------
// A in per-lane mma-fragment order: [q][wm][ks][mf][lane] uint4 (fp16 pairs)
__device__ __align__(16) uint4 g_AfH[NCHUNK*4*4*2*32];
__device__ __align__(16) uint4 g_AfL[NCHUNK*4*4*2*32];
__device__ __align__(16) __half g_xh[BB*CI*HH*PXW];
__device__ __align__(16) float g_attn[BB*HH*KK*WW];

#define SWZ(o) ((o) ^ (((o) >> 3) & 0x70))

// ---------------- PTX helpers (baseline ISA, sm_80+) -----------------------
__device__ __forceinline__ u32 smem_u32(const void* p) {
    u32 a;
    asm("{ .reg .u64 t; cvta.to.shared.u64 t, %1; cvt.u32.u64 %0, t; }"
        : "=r"(a) : "l"(p));
    return a;
}
__device__ __forceinline__ void cpasync16(u32 dst, const void* src, u32 srcsize) {
    u64 gsrc = (u64)__cvta_generic_to_global(src);
    asm volatile("cp.async.cg.shared.global [%0], [%1], 16, %2;"
                 :: "r"(dst), "l"(gsrc), "r"(srcsize) : "memory");
}
#define CP_COMMIT() asm volatile("cp.async.commit_group;" ::: "memory")

__device__ __forceinline__ void ldm_x4(u32* r, u32 addr) {
    asm volatile("ldmatrix.sync.aligned.m8n8.x4.shared.b16 {%0,%1,%2,%3}, [%4];"
        : "=r"(r[0]), "=r"(r[1]), "=r"(r[2]), "=r"(r[3]) : "r"(addr));
}
__device__ __forceinline__ void ldm_x2(u32* r, u32 addr) {
    asm volatile("ldmatrix.sync.aligned.m8n8.x2.shared.b16 {%0,%1}, [%2];"
        : "=r"(r[0]), "=r"(r[1]) : "r"(addr));
}
__device__ __forceinline__ void mma16816h(float* c, const u32* a, const u32* b) {
    asm volatile("mma.sync.aligned.m16n8k16.row.col.f32.f16.f16.f32 "
        "{%0,%1,%2,%3}, {%4,%5,%6,%7}, {%8,%9}, {%0,%1,%2,%3};"
        : "+f"(c[0]), "+f"(c[1]), "+f"(c[2]), "+f"(c[3])
        : "r"(a[0]), "r"(a[1]), "r"(a[2]), "r"(a[3]), "r"(b[0]), "r"(b[1]));
}
#define MB_INIT(mb, n) asm volatile("mbarrier.init.shared.b64 [%0], %1;" :: "r"(mb), "r"((u32)(n)) : "memory")
#define MB_ARRIVE(mb)  asm volatile("mbarrier.arrive.shared.b64 _, [%0];" :: "r"(mb) : "memory")

__device__ __forceinline__ void mb_wait(u32 mb, u32 parity) {
    asm volatile(
        "{\n\t.reg .pred P1;\n\t"
        "WL_%=:\n\t"
        "mbarrier.try_wait.parity.acquire.cta.shared::cta.b64 P1, [%0], %1, 0x989680;\n\t"
        "@P1 bra.uni WD_%=;\n\t"
        "bra.uni WL_%=;\n\t"
        "WD_%=:\n\t}"
        :: "r"(mb), "r"(parity) : "memory");
}

__device__ __forceinline__ unsigned short hfu(float v) {
    __half h = __float2half(v);
    return *(unsigned short*)&h;
}

// ---------------- prep: W1 -> fp16 hi/lo A fragments -----------------------
// grid (196, 4), block 256: tid -> ks(2b) mf(1b) lane(5b)
__global__ void k_prepw(const float* __restrict__ W1) {
    int q = blockIdx.x, wm = blockIdx.y;
    int tid = threadIdx.x;
    int ks = tid >> 6, mf = (tid >> 5) & 1, lane = tid & 31;
    int m  = wm * 32 + mf * 16 + (lane >> 2);
    int k0 = q * KC + ks * 16 + (lane & 3) * 2;
    const float* w0 = W1 + (size_t)m * KTOT + k0;
    const float* w1 = W1 + (size_t)(m + 8) * KTOT + k0;
    float v[8] = { w0[0], w0[1], w1[0], w1[1], w0[8], w0[9], w1[8], w1[9] };
    u32 h[4], l[4];
    #pragma unroll
    for (int i = 0; i < 4; i++) {
        float a = v[2*i], b = v[2*i+1];
        unsigned short ah = hfu(a), bh = hfu(b);
        float ar = a - __half2float(*(__half*)&ah);
        float br = b - __half2float(*(__half*)&bh);
        h[i] = (u32)ah | ((u32)bh << 16);
        l[i] = (u32)hfu(ar) | ((u32)hfu(br) << 16);
    }
    size_t off = ((((size_t)q * 4 + wm) * 4 + ks) * 2 + mf) * 32 + lane;
    g_AfH[off] = make_uint4(h[0], h[1], h[2], h[3]);
    g_AfL[off] = make_uint4(l[0], l[1], l[2], l[3]);
}

// ---------------- prep: x -> padded fp16 plane -----------------------------
__global__ void k_prepx(const float* __restrict__ x) {
    int idx = blockIdx.x * 128 + threadIdx.x;   // over BB*CI*HH rows
    if (idx >= BB * CI * HH) return;
    const float* row = x + (size_t)idx * WW;
    __align__(16) __half h[PXW];
    #pragma unroll
    for (int i = 0; i < PXW; i++) {
        int gx = i - 6;
        float v = (gx >= 0 && gx < WW) ? row[gx] : 0.f;
        h[i] = __float2half(v);
    }
    uint4* dh = (uint4*)((char*)g_xh + (size_t)idx * PXW * 2);
    #pragma unroll
    for (int s = 0; s < 9; s++) dh[s] = ((uint4*)h)[s];
}

// ---------------- conv1 + attn fused (fp16 2-term) -------------------------
// 384 threads: warps 0-7 consumers (mma), warps 8-11 producers (stage+gather)
#define XS_SZ  6048               // 42 rows * 144B
#define TILE_B 14336              // 112 rows * 128B
#define SM_XS  64                 // after mbarriers; 4 xs buffers
#define SM_B   (SM_XS + 4*XS_SZ)  // 24256; 2 B buffers -> ends 52928
// epilogue: ls @64 (21952B), W2s @22016 (25088B), O1s @47104 (57344B)
#define EP_LS  64
#define EP_W2  (EP_LS + 49*112*4)         // 22016
#define EP_O1  (EP_W2 + 49*128*4)         // 47104
#define SM_TOTAL (EP_O1 + 128*112*4)      // 104448

__global__ void __launch_bounds__(384, 1) k_conv1(const float* __restrict__ b1,
                                                  const float* __restrict__ W2,
                                                  const float* __restrict__ b2) {
    extern __shared__ char smem[];
    u32 sb = smem_u32(smem);
    int tid = threadIdx.x, wid = tid >> 5, lane = tid & 31;
    int rp = blockIdx.x, b = blockIdx.y;
    int y0 = rp * 2;

    if (tid == 0) {
        MB_INIT(sb + 0, 128);  MB_INIT(sb + 8, 128);    // full[0], full[1]
        MB_INIT(sb + 16, 256); MB_INIT(sb + 24, 256);   // free[0], free[1]
    }
    __syncthreads();

    float acc[56];
    #pragma unroll
    for (int i = 0; i < 56; i++) acc[i] = 0.f;

    if (wid < 8) {
        // ======================= CONSUMERS =======================
        int wm = wid & 3, wn = wid >> 2;

        u32 xorm  = (u32)(lane & 7) << 4;
        u32 bRow4 = (u32)(wn * 56 + ((lane >> 4) << 3) + (lane & 7)) * 128;
        u32 bRow2 = (u32)(wn * 56 + 48 + (lane & 7)) * 128;
        u32 bCol  = (u32)((lane >> 3) & 1) * 16;
        u32 fullph[2] = {0, 0};

        for (int q = 0; q < NCHUNK; q++) {
            int p = q & 1;
            // prefetch A fragments (overlaps the full-wait)
            const uint4* ph = g_AfH + ((size_t)q * 4 + wm) * 256 + lane;
            const uint4* pl = g_AfL + ((size_t)q * 4 + wm) * 256 + lane;
            uint4 AH[8], AL[8];          // s = ks*2+mf
            #pragma unroll
            for (int s = 0; s < 8; s++) { AH[s] = ph[s * 32]; AL[s] = pl[s * 32]; }

            mb_wait(sb + p * 8, fullph[p]); fullph[p] ^= 1;

            u32 Bh = sb + SM_B + p * TILE_B;
            #pragma unroll
            for (int ks = 0; ks < 4; ks++) {
                u32 colB = ((u32)(ks * 32) + bCol) ^ xorm;
                u32 bh[14];
                #pragma unroll
                for (int pp = 0; pp < 3; pp++)
                    ldm_x4(&bh[4 * pp], Bh + bRow4 + pp * 2048 + colB);
                ldm_x2(&bh[12], Bh + bRow2 + colB);
                #pragma unroll
                for (int mf = 0; mf < 2; mf++) {
                    const u32* ah = (const u32*)&AH[ks * 2 + mf];
                    const u32* al = (const u32*)&AL[ks * 2 + mf];
                    #pragma unroll
                    for (int nf = 0; nf < 7; nf++) {
                        float* c = &acc[(mf * 7 + nf) * 4];
                        mma16816h(c, ah, &bh[2 * nf]);
                        mma16816h(c, al, &bh[2 * nf]);
                    }
                }
            }
            MB_ARRIVE(sb + 16 + p * 8);
        }
    } else {
        // ======================= PRODUCERS (4 warps, 128 threads) =========
        int ptid = tid - 256;     // 0..127

        auto stage_xs = [&](int q) {
            int c0 = (q * KC) / KK;
            u32 xb = sb + SM_XS + (q & 3) * XS_SZ;
            for (int s = ptid; s < 378; s += 128) {
                int rowi = s / 9, seg = s % 9;
                int cc = rowi / 14, r = rowi % 14;
                int cp = c0 + cc, gy = y0 - 6 + r;
                bool v = (gy >= 0 && gy < HH && cp < CI);
                const char* src = (const char*)g_xh +
                    ((size_t)((b * CI + (v ? cp : 0)) * HH + (v ? gy : 0)) * PXW) * 2 + seg * 16;
                cpasync16(xb + (cc * 14 + r) * 144 + seg * 16, src, v ? 16u : 0u);
            }
        };

        stage_xs(0); CP_COMMIT();
        stage_xs(1); CP_COMMIT();
        u32 freeph[2] = {0, 0};

        for (int q = 0; q < NCHUNK; q++) {
            int p = q & 1;
            if (q >= 2) { mb_wait(sb + 16 + p * 8, freeph[p]); freeph[p] ^= 1; }
            if (q + 2 < NCHUNK) stage_xs(q + 2);
            CP_COMMIT();
            asm volatile("cp.async.wait_group 2;" ::: "memory");
            asm volatile("bar.sync 1, 128;" ::: "memory");

            // gather B[q] (hi only) on 128 threads
            int k0 = q * KC, c0 = k0 / KK, t00 = k0 - KK * c0;
            const char* xbase = smem + SM_XS + (q & 3) * XS_SZ;
            char* Bt = smem + SM_B + p * TILE_B;
            for (int gn = ptid; gn < 112; gn += 128) {
                int gdy = gn / 56, gxn = gn % 56;
                int tj = t00 % 7;
                int idx = (gdy + 2 * (t00 / 7)) * PXW + gxn + 2 * tj;
                u32 rowoff = (u32)(gn * 128);
                #pragma unroll
                for (int g = 0; g < 8; g++) {
                    u32 v[4];
                    #pragma unroll
                    for (int h2 = 0; h2 < 4; h2++) {
                        u32 a = *(const unsigned short*)(xbase + idx * 2);
                        idx += (tj == 6) ? 132 : 2; tj = (tj == 6) ? 0 : tj + 1;
                        u32 bb = *(const unsigned short*)(xbase + idx * 2);
                        idx += (tj == 6) ? 132 : 2; tj = (tj == 6) ? 0 : tj + 1;
                        v[h2] = a | (bb << 16);
                    }
                    *(uint4*)(Bt + SWZ(rowoff + g * 16)) = *(uint4*)v;
                }
            }
            MB_ARRIVE(sb + p * 8);   // full[p]
        }
    }

    // ======================= FUSED ATTN EPILOGUE =======================
    __syncthreads();    // everyone done; all mainloop buffers now dead
    {
        float* ls  = (float*)(smem + EP_LS);    // [49][112]
        float* W2s = (float*)(smem + EP_W2);    // [49][128]
        float* O1s = (float*)(smem + EP_O1);    // [128][112]

        if (wid < 8) {
            int wm = wid & 3, wn = wid >> 2;
            #pragma unroll
            for (int mf = 0; mf < 2; mf++) {
                int m = wm * 32 + mf * 16 + (lane >> 2);
                float bia0 = b1[m], bia8 = b1[m + 8];
                #pragma unroll
                for (int nf = 0; nf < 7; nf++) {
                    float* c = &acc[(mf * 7 + nf) * 4];
                    int n = wn * 56 + nf * 8 + 2 * (lane & 3);
                    O1s[m * 112 + n]           = c[0] + bia0;
                    O1s[m * 112 + n + 1]       = c[1] + bia0;
                    O1s[(m + 8) * 112 + n]     = c[2] + bia8;
                    O1s[(m + 8) * 112 + n + 1] = c[3] + bia8;
                }
            }
        }
        for (int s = tid; s < (KK * CO) / 4; s += 384)
            *(float4*)&W2s[4 * s] = *(const float4*)&W2[4 * s];
        __syncthreads();

        // logits: ls[k][n] = b2[k] + sum_c W2[k][c] * O1s[c][n]
        for (int p = tid; p < KK * 112; p += 384) {
            int k = p / 112, n = p - k * 112;
            float a = b2[k];
            const float* wrow = &W2s[k * 128];
            #pragma unroll 4
            for (int c = 0; c < 128; c++)
                a += wrow[c] * O1s[c * 112 + n];
            ls[p] = a;
        }
        __syncthreads();

        // softmax over k, per column n; write g_attn
        if (tid < 112) {
            int n = tid;
            float mx = -1e30f;
            #pragma unroll
            for (int k = 0; k < KK; k++) mx = fmaxf(mx, ls[k * 112 + n]);
            float ssum = 0.f;
            #pragma unroll
            for (int k = 0; k < KK; k++) {
                float e = __expf(ls[k * 112 + n] - mx);
                ls[k * 112 + n] = e;
                ssum += e;
            }
            float inv = 1.f / ssum;
            int row = n / 56, xc = n - (n / 56) * 56;
            float* ga = g_attn + (size_t)(b * HH + y0 + row) * KK * WW;
            #pragma unroll
            for (int k = 0; k < KK; k++)
                ga[k * WW + xc] = ls[k * 112 + n] * inv;
        }
    }
}

// ---------------- k_wsum: weighted patch sum -------------------------------
// grid (8, 56, 4), 224 threads = 28 px-pairs x 8 ch-groups of 4. 32 ch/block.
// float2 vectorization: thread computes 2 px x 4 ch.
#define WS_SMEM ((49*56 + 32*7*72) * 4)   // 75488 B

__global__ void __launch_bounds__(224) k_wsum(const float* __restrict__ x,
                                              float* __restrict__ out) {
    extern __shared__ float sm[];
    float* as = sm;              // [49][56] attn
    float* xs = sm + 49 * 56;    // [32][7][72]

    int tid = threadIdx.x;
    int cg = blockIdx.x, y = blockIdx.y, b = blockIdx.z;

    // as: straight float4 copy (2744 floats = 686 float4)
    const float* ga = g_attn + (size_t)(b * HH + y) * KK * WW;
    for (int s = tid; s < 686; s += 224)
        ((float4*)as)[s] = ((const float4*)ga)[s];

    // xs staging: thread owns (i, s2), loops over 32 channels incrementally
    {
        int i0 = tid / 34, s20 = tid % 34;    // i0 in [0,6], tail below
        #pragma unroll
        for (int pass = 0; pass < 2; pass++) {
            int ii, ss;
            if (pass == 0) { ii = i0; ss = s20; }
            else { if (tid >= 14) break; ii = 6; ss = 20 + tid; }
            int gx = 2 * ss - 6, gy = y - 6 + 2 * ii;
            bool v = (gy >= 0 && gy < HH && gx >= 0 && gx < WW);
            const float* src = &x[(size_t)((b * CI + cg * 32) * HH +
                                           (v ? gy : 0)) * WW + (v ? gx : 0)];
            float* dst = &xs[ii * 72 + 2 * ss];
            if (v) {
                #pragma unroll 8
                for (int c = 0; c < 32; c++)
                    *(float2*)&dst[c * 7 * 72] = *(const float2*)&src[c * HH * WW];
            } else {
                #pragma unroll 8
                for (int c = 0; c < 32; c++)
                    *(float2*)&dst[c * 7 * 72] = make_float2(0.f, 0.f);
            }
        }
    }
    __syncthreads();

    int pp = tid % 28;           // px pair -> xc = 2*pp
    int cl = tid / 28;           // 0..7 -> channels cl*4..cl*4+3
    int x0 = 2 * pp;

    float2 acc[4];
    #pragma unroll
    for (int q = 0; q < 4; q++) acc[q] = make_float2(0.f, 0.f);

    const float* xb0 = &xs[(cl * 4) * 7 * 72 + x0];
    const float* ab0 = &as[x0];

    #pragma unroll
    for (int i = 0; i < 7; i++) {
        #pragma unroll
        for (int j = 0; j < 7; j++) {
            float2 a2 = *(const float2*)&ab0[(7 * i + j) * 56];
            #pragma unroll
            for (int q = 0; q < 4; q++) {
                float2 xv = *(const float2*)&xb0[(q * 7 + i) * 72 + 2 * j];
                acc[q].x += a2.x * xv.x;
                acc[q].y += a2.y * xv.y;
            }
        }
    }

    #pragma unroll
    for (int q = 0; q < 4; q++) {
        int c = cg * 32 + cl * 4 + q;
        *(float2*)&out[(size_t)((b * CI + c) * HH + y) * WW + x0] = acc[q];
    }
}

// ---------------------------------------------------------------------------
extern "C" void kernel_launch(void* const* d_in, const int* in_sizes, int n_in,
                              void* d_out, int out_size) {
    const float* x  = (const float*)d_in[0];
    const float* W1 = (const float*)d_in[1];
    const float* b1 = (const float*)d_in[2];
    const float* W2 = (const float*)d_in[3];
    const float* b2 = (const float*)d_in[4];
    float* out = (float*)d_out;
    (void)in_sizes; (void)n_in; (void)out_size;

    k_prepw<<<dim3(NCHUNK, 4), 256>>>(W1);
    k_prepx<<<(BB * CI * HH + 127) / 128, 128>>>(x);

    cudaFuncSetAttribute(k_conv1, cudaFuncAttributeMaxDynamicSharedMemorySize,
                         SM_TOTAL);
    dim3 g1(28, BB);
    k_conv1<<<g1, 384, SM_TOTAL>>>(b1, W2, b2);

    cudaFuncSetAttribute(k_wsum, cudaFuncAttributeMaxDynamicSharedMemorySize,
                         WS_SMEM);
    dim3 g3(8, HH, BB);
    k_wsum<<<g3, 224, WS_SMEM>>>(x, out);
}